// round 8
// baseline (speedup 1.0000x reference)
#include <cuda_runtime.h>
#include <cuda_bf16.h>
#include <math.h>

// PositionalEmbedding: out[l, :] = emb_table[token_ids[l], :] + PE(l, :)
// PE pairs p in [0,255): col 2p = sin(l / 10000^(2p/512)), col 2p+1 = cos(...).
// Cols 510, 511 get PE = 0 (reference only fills 255 pairs).
//
// The per-pair frequency table w_p = 10000^(2p/512) (fp32, rounded from a
// double-precision exp) is computed on the HOST at capture time and passed as
// a 1KB kernel parameter (__grid_constant__, lives in the constant bank) —
// this removes the separate setup kernel from the captured graph.

#define SEQ   131072
#define DEPTH 512
#define ROWS_PER_GROUP 8   // rows handled by each 128-thread group

struct WTab { float w[256]; };

// Accurate sin/cos of the fp32-rounded angle a = fl32(fi / w), mimicking
// jnp.sin/jnp.cos applied to the reference's fp32 angle.
//  - __fdiv_rn: IEEE round-to-nearest division (matches reference's angle bits)
//  - two-word Cody-Waite reduction mod 2pi (k <= 20861 for a <= 131071)
//  - MUFU sin/cos on the reduced argument |r| <= pi + 0.01
__device__ __forceinline__ float2 pe_pair(float fi, float w) {
    float a = __fdiv_rn(fi, w);
    float k = rintf(a * 0.15915494309189535f);
    // 2pi = HI + MID; HI = fl32(2pi), MID = 2pi - HI = -1.7484555e-7
    float r = fmaf(k, -6.283185307179586f, a);   // literal rounds to HI
    r = fmaf(k, 1.7484556e-07f, r);              // add back k*(HI - 2pi)
    float s, c;
    __sincosf(r, &s, &c);
    return make_float2(s, c);
}

__global__ void __launch_bounds__(256) emb_pe_kernel(
    const int*   __restrict__ tok,
    const float* __restrict__ tab,
    float*       __restrict__ out,
    const __grid_constant__ WTab wt)
{
    const int tid  = threadIdx.x;
    const unsigned t    = tid & 127;             // float4 index within a row
    const int grp  = tid >> 7;                   // 0 or 1
    const int base = (blockIdx.x * 2 + grp) * ROWS_PER_GROUP;

    // ---- 8 token ids via two coalesced int4 loads (base is 8-aligned) ----
    const int4 tka = __ldg(reinterpret_cast<const int4*>(tok + base));
    const int4 tkb = __ldg(reinterpret_cast<const int4*>(tok + base + 4));
    const unsigned tk[ROWS_PER_GROUP] = {
        (unsigned)tka.x, (unsigned)tka.y, (unsigned)tka.z, (unsigned)tka.w,
        (unsigned)tkb.x, (unsigned)tkb.y, (unsigned)tkb.z, (unsigned)tkb.w};

    // 32-bit byte offsets: table is 103MB, output 268MB — both < 4GB.
    const char* tabb = reinterpret_cast<const char*>(tab);
    char*       outb = reinterpret_cast<char*>(out);
    const unsigned tb = t << 4;                  // byte offset of this thread's float4

    // ---- front-batched independent table gathers (2KB-aligned rows) ----
    float4 e[ROWS_PER_GROUP];
#pragma unroll
    for (int r = 0; r < ROWS_PER_GROUP; r++)
        e[r] = __ldg(reinterpret_cast<const float4*>(tabb + ((tk[r] << 11) + tb)));

    // frequencies for pairs p0 = 2t, p1 = 2t+1 — one LDC.64 from param space
    const float w0   = wt.w[2 * t];
    const float w1   = wt.w[2 * t + 1];
    const bool  tail = (t == 127);               // pair 255 -> PE = 0

    unsigned ob = (((unsigned)base) << 11) + tb; // output byte offset, row 'base'
#pragma unroll
    for (int r = 0; r < ROWS_PER_GROUP; r++) {
        const float fi = (float)(base + r);
        float4 o;
        {
            float2 sc = pe_pair(fi, w0);         // pair 2t (always < 255)
            o.x = e[r].x + sc.x;
            o.y = e[r].y + sc.y;
        }
        if (!tail) {
            float2 sc = pe_pair(fi, w1);         // pair 2t+1
            o.z = e[r].z + sc.x;
            o.w = e[r].w + sc.y;
        } else {
            o.z = e[r].z;
            o.w = e[r].w;
        }
        // Streaming store: keep the 268MB output stream from displacing the
        // embedding table's L2 working set.
        __stcs(reinterpret_cast<float4*>(outb + ob), o);
        ob += 2048;                              // next row
    }
}

extern "C" void kernel_launch(void* const* d_in, const int* in_sizes, int n_in,
                              void* d_out, int out_size) {
    const int*   tok = (const int*)d_in[0];     // token_ids, int32 [131072]
    const float* tab = (const float*)d_in[1];   // emb_table, fp32 [50257, 512]
    float*       out = (float*)d_out;           // fp32 [131072, 512]

    // Host-side frequency table (runs at capture time; replays see the
    // baked-in parameter). Same math as the former device setup kernel:
    // w_p = exp((2p/512)*ln(10000)) in double, rounded to fp32.
    WTab wt;
    for (int p = 0; p < 255; p++) {
        double y = (double)(2 * p) / 512.0;      // exact in double
        wt.w[p] = (float)exp(y * 9.210340371976184);  // ln(10000)
    }
    wt.w[255] = 1.0f;                            // unused (guarded)

    emb_pe_kernel<<<SEQ / (2 * ROWS_PER_GROUP), 256>>>(tok, tab, out, wt);
}